// round 14
// baseline (speedup 1.0000x reference)
#include <cuda_runtime.h>

// BiLingual dual EmbeddingBag(sum)
//   inputs_pri: int32 [4096, 200]
//   inputs_sec: int32 [4096, 200]
//   emb_pri:    f32   [100000, 64]   (rows 256B)
//   emb_sec:    f32   [100000, 64]
//   out:        f32   [2, 4096, 64]
//
// Champion (R2, 25.1us) + int4 index consumption, L1 policy untouched.
// One warp per bag. Half-warp h sums tokens [100h, 100h+100): lanes hold a
// float4 dim-quad (16 lanes = 256B row), so each LDG.128 gathers one row per
// half-warp. Indices staged in smem; consumed as int4 -> 1 LDS.128 broadcast
// feeds 4 LDG.128s. Halves combined at the end via shfl_xor 16.

#define EB_B 4096
#define EB_S 200
#define EB_D 64
#define WPB 8
#define SROW 208                     // padded ints per warp (16B-aligned rows)
#define NBLK_PER_TAB (EB_B / WPB)    // 512

__global__ __launch_bounds__(WPB * 32)
void embed_sum_kernel(const int* __restrict__ idx_pri,
                      const int* __restrict__ idx_sec,
                      const float* __restrict__ emb_pri,
                      const float* __restrict__ emb_sec,
                      float* __restrict__ out) {
    __shared__ __align__(16) int sidx[WPB * SROW];

    const int tid  = threadIdx.x;
    const int warp = tid >> 5;
    const int lane = tid & 31;
    const int half = lane >> 4;      // token-range half
    const int hl   = lane & 15;      // dim quad within row

    const int*    idx;
    const float4* tab;
    int           row_base;
    if (blockIdx.x < NBLK_PER_TAB) {
        idx      = idx_pri;
        tab      = reinterpret_cast<const float4*>(emb_pri);
        row_base = blockIdx.x * WPB;
    } else {
        idx      = idx_sec;
        tab      = reinterpret_cast<const float4*>(emb_sec);
        row_base = (blockIdx.x - NBLK_PER_TAB) * WPB;
    }

    // Stage this block's 8x200 indices (coalesced), padded rows.
    {
        const int* gsrc = idx + row_base * EB_S;
        #pragma unroll
        for (int i = tid; i < WPB * EB_S; i += WPB * 32) {
            const int r = i / EB_S;
            const int c = i - r * EB_S;
            sidx[r * SROW + c] = gsrc[i];
        }
    }
    __syncthreads();

    // Half h consumes ints [100h, 100h+100) as 25 int4 groups.
    const int4* myv =
        reinterpret_cast<const int4*>(sidx + warp * SROW + half * 100);

    float4 a0 = make_float4(0.f, 0.f, 0.f, 0.f);
    float4 a1 = make_float4(0.f, 0.f, 0.f, 0.f);

    // 25 groups of 4 tokens; unroll 2 -> up to 8 LDG.128 in flight.
    #pragma unroll 2
    for (int g = 0; g < 25; ++g) {
        const int4 id4 = myv[g];
        const float4 v0 = __ldg(&tab[id4.x * (EB_D / 4) + hl]);
        const float4 v1 = __ldg(&tab[id4.y * (EB_D / 4) + hl]);
        const float4 v2 = __ldg(&tab[id4.z * (EB_D / 4) + hl]);
        const float4 v3 = __ldg(&tab[id4.w * (EB_D / 4) + hl]);
        a0.x += v0.x; a0.y += v0.y; a0.z += v0.z; a0.w += v0.w;
        a1.x += v1.x; a1.y += v1.y; a1.z += v1.z; a1.w += v1.w;
        a0.x += v2.x; a0.y += v2.y; a0.z += v2.z; a0.w += v2.w;
        a1.x += v3.x; a1.y += v3.y; a1.z += v3.z; a1.w += v3.w;
    }

    float4 acc;
    acc.x = a0.x + a1.x;
    acc.y = a0.y + a1.y;
    acc.z = a0.z + a1.z;
    acc.w = a0.w + a1.w;

    // Combine the two token-range halves (lane l <-> l^16: same bag, same quad).
    acc.x += __shfl_xor_sync(0xffffffffu, acc.x, 16);
    acc.y += __shfl_xor_sync(0xffffffffu, acc.y, 16);
    acc.z += __shfl_xor_sync(0xffffffffu, acc.z, 16);
    acc.w += __shfl_xor_sync(0xffffffffu, acc.w, 16);

    if (half == 0) {
        const int out_row =
            (blockIdx.x < NBLK_PER_TAB ? 0 : EB_B) + row_base + warp;
        reinterpret_cast<float4*>(out)[out_row * (EB_D / 4) + hl] = acc;
    }
}

extern "C" void kernel_launch(void* const* d_in, const int* in_sizes, int n_in,
                              void* d_out, int out_size) {
    const int*   idx_pri = (const int*)d_in[0];
    const int*   idx_sec = (const int*)d_in[1];
    const float* emb_pri = (const float*)d_in[2];
    const float* emb_sec = (const float*)d_in[3];
    float* outp = (float*)d_out;

    embed_sum_kernel<<<2 * NBLK_PER_TAB, WPB * 32>>>(
        idx_pri, idx_sec, emb_pri, emb_sec, outp);
}

// round 15
// speedup vs baseline: 1.2252x; 1.2252x over previous
#include <cuda_runtime.h>

// BiLingual dual EmbeddingBag(sum)
//   inputs_pri: int32 [4096, 200]
//   inputs_sec: int32 [4096, 200]
//   emb_pri:    f32   [100000, 64]   (rows 256B)
//   emb_sec:    f32   [100000, 64]
//   out:        f32   [2, 4096, 64]
//
// Champion structure (R2, 25.1us) preserved exactly: one warp per bag,
// token-PAIR per LDG.128 (half h of the warp loads token j+h; 16 lanes x
// 16B = one 256B row), indices staged in smem, 4 LDGs in flight.
// R8 change: indices consumed as int4 (tokens 4g..4g+3 = two pair-iters);
// per-half token selected with SEL (ALU) instead of a second LDS.
// MIO ops per gather: 1.0 -> 0.5.

#define EB_B 4096
#define EB_S 200
#define EB_D 64
#define WPB 8
#define NBLK_PER_TAB (EB_B / WPB)   // 512

__global__ __launch_bounds__(WPB * 32)
void embed_sum_kernel(const int* __restrict__ idx_pri,
                      const int* __restrict__ idx_sec,
                      const float* __restrict__ emb_pri,
                      const float* __restrict__ emb_sec,
                      float* __restrict__ out) {
    __shared__ __align__(16) int sidx[WPB * EB_S];

    const int tid  = threadIdx.x;
    const int warp = tid >> 5;
    const int lane = tid & 31;
    const int half = lane >> 4;     // which token of the pair
    const int hl   = lane & 15;     // dim quad within row

    const int*    idx;
    const float4* tab;
    int           row_base;
    if (blockIdx.x < NBLK_PER_TAB) {
        idx      = idx_pri;
        tab      = reinterpret_cast<const float4*>(emb_pri);
        row_base = blockIdx.x * WPB;
    } else {
        idx      = idx_sec;
        tab      = reinterpret_cast<const float4*>(emb_sec);
        row_base = (blockIdx.x - NBLK_PER_TAB) * WPB;
    }

    // Stage this block's 8x200 indices (coalesced).
    {
        const int* gsrc = idx + row_base * EB_S;
        #pragma unroll
        for (int i = tid; i < WPB * EB_S; i += WPB * 32)
            sidx[i] = gsrc[i];
    }
    __syncthreads();

    // Warp's indices as int4 groups: group g = tokens 4g..4g+3 (50 groups).
    const int4* myv = reinterpret_cast<const int4*>(sidx + warp * EB_S);

    float4 a0 = make_float4(0.f, 0.f, 0.f, 0.f);
    float4 a1 = make_float4(0.f, 0.f, 0.f, 0.f);

    // 50 groups x 2 pair-iterations; unroll 2 -> 4 LDG.128 in flight
    // (same in-flight depth and gather order as the 25.1us champion).
    #pragma unroll 2
    for (int g = 0; g < EB_S / 4; ++g) {
        const int4 q = myv[g];
        const int idA = half ? q.y : q.x;   // pair-iteration 0 (tokens 4g,4g+1)
        const int idB = half ? q.w : q.z;   // pair-iteration 1 (tokens 4g+2,4g+3)
        const float4 v0 = __ldg(&tab[idA * (EB_D / 4) + hl]);
        const float4 v1 = __ldg(&tab[idB * (EB_D / 4) + hl]);
        a0.x += v0.x; a0.y += v0.y; a0.z += v0.z; a0.w += v0.w;
        a1.x += v1.x; a1.y += v1.y; a1.z += v1.z; a1.w += v1.w;
    }

    float4 acc;
    acc.x = a0.x + a1.x;
    acc.y = a0.y + a1.y;
    acc.z = a0.z + a1.z;
    acc.w = a0.w + a1.w;

    // Combine the two half-warp partials (same bag, same dim quad).
    acc.x += __shfl_xor_sync(0xffffffffu, acc.x, 16);
    acc.y += __shfl_xor_sync(0xffffffffu, acc.y, 16);
    acc.z += __shfl_xor_sync(0xffffffffu, acc.z, 16);
    acc.w += __shfl_xor_sync(0xffffffffu, acc.w, 16);

    if (half == 0) {
        const int out_row =
            (blockIdx.x < NBLK_PER_TAB ? 0 : EB_B) + row_base + warp;
        reinterpret_cast<float4*>(out)[out_row * (EB_D / 4) + hl] = acc;
    }
}

extern "C" void kernel_launch(void* const* d_in, const int* in_sizes, int n_in,
                              void* d_out, int out_size) {
    const int*   idx_pri = (const int*)d_in[0];
    const int*   idx_sec = (const int*)d_in[1];
    const float* emb_pri = (const float*)d_in[2];
    const float* emb_sec = (const float*)d_in[3];
    float* outp = (float*)d_out;

    embed_sum_kernel<<<2 * NBLK_PER_TAB, WPB * 32>>>(
        idx_pri, idx_sec, emb_pri, emb_sec, outp);
}

// round 16
// speedup vs baseline: 1.2267x; 1.0012x over previous
#include <cuda_runtime.h>

// BiLingual dual EmbeddingBag(sum)
//   inputs_pri: int32 [4096, 200]
//   inputs_sec: int32 [4096, 200]
//   emb_pri:    f32   [100000, 64]   (rows 256B)
//   emb_sec:    f32   [100000, 64]
//   out:        f32   [2, 4096, 64]
//
// One warp per bag. LDG.256 gathers: oct = lane>>3 picks one of 4 tokens,
// lanes ol=0..7 each load 32B -> 8 lanes cover one 256B row, 4 rows per
// warp-load. Table loads tagged L2::evict_last so the 51MB table set stays
// L2-resident across graph replays (kills the ~51MB/launch DRAM refill).
// Indices staged in smem; one LDS.32 broadcast per gather group.

#define EB_B 4096
#define EB_S 200
#define EB_D 64
#define WPB 8
#define NBLK_PER_TAB (EB_B / WPB)   // 512

__device__ __forceinline__ void ldg256_el(const float* p, float* v) {
    unsigned r0, r1, r2, r3, r4, r5, r6, r7;
    asm("ld.global.nc.L2::evict_last.v8.b32 {%0,%1,%2,%3,%4,%5,%6,%7}, [%8];"
        : "=r"(r0), "=r"(r1), "=r"(r2), "=r"(r3),
          "=r"(r4), "=r"(r5), "=r"(r6), "=r"(r7)
        : "l"(p));
    v[0] = __uint_as_float(r0); v[1] = __uint_as_float(r1);
    v[2] = __uint_as_float(r2); v[3] = __uint_as_float(r3);
    v[4] = __uint_as_float(r4); v[5] = __uint_as_float(r5);
    v[6] = __uint_as_float(r6); v[7] = __uint_as_float(r7);
}

__global__ __launch_bounds__(WPB * 32)
void embed_sum_kernel(const int* __restrict__ idx_pri,
                      const int* __restrict__ idx_sec,
                      const float* __restrict__ emb_pri,
                      const float* __restrict__ emb_sec,
                      float* __restrict__ out) {
    __shared__ __align__(16) int sidx[WPB * EB_S];

    const int tid  = threadIdx.x;
    const int warp = tid >> 5;
    const int lane = tid & 31;
    const int oct  = lane >> 3;     // which token of the group of 4
    const int ol   = lane & 7;      // 32B chunk within the 256B row

    const int*   idx;
    const float* tab;
    int          row_base;
    if (blockIdx.x < NBLK_PER_TAB) {
        idx      = idx_pri;
        tab      = emb_pri;
        row_base = blockIdx.x * WPB;
    } else {
        idx      = idx_sec;
        tab      = emb_sec;
        row_base = (blockIdx.x - NBLK_PER_TAB) * WPB;
    }

    // Stage this block's 8x200 indices (coalesced).
    {
        const int* gsrc = idx + row_base * EB_S;
        #pragma unroll
        for (int i = tid; i < WPB * EB_S; i += WPB * 32)
            sidx[i] = gsrc[i];
    }
    __syncthreads();

    const int* my = &sidx[warp * EB_S];

    float acc[8];
    #pragma unroll
    for (int i = 0; i < 8; ++i) acc[i] = 0.f;

    // 50 groups of 4 tokens; unroll 2 -> 2 LDG.256 (8 rows) in flight.
    #pragma unroll 2
    for (int g = 0; g < EB_S / 4; ++g) {
        const int id = my[4 * g + oct];
        float v[8];
        ldg256_el(tab + id * EB_D + ol * 8, v);
        #pragma unroll
        for (int i = 0; i < 8; ++i) acc[i] += v[i];
    }

    // Reduce the 4 token-partials (lanes with equal ol across octs).
    #pragma unroll
    for (int i = 0; i < 8; ++i) {
        acc[i] += __shfl_xor_sync(0xffffffffu, acc[i], 8);
        acc[i] += __shfl_xor_sync(0xffffffffu, acc[i], 16);
    }

    if (oct == 0) {
        const int out_row =
            (blockIdx.x < NBLK_PER_TAB ? 0 : EB_B) + row_base + warp;
        float4* o = reinterpret_cast<float4*>(out + out_row * EB_D + ol * 8);
        o[0] = make_float4(acc[0], acc[1], acc[2], acc[3]);
        o[1] = make_float4(acc[4], acc[5], acc[6], acc[7]);
    }
}

extern "C" void kernel_launch(void* const* d_in, const int* in_sizes, int n_in,
                              void* d_out, int out_size) {
    const int*   idx_pri = (const int*)d_in[0];
    const int*   idx_sec = (const int*)d_in[1];
    const float* emb_pri = (const float*)d_in[2];
    const float* emb_sec = (const float*)d_in[3];
    float* outp = (float*)d_out;

    embed_sum_kernel<<<2 * NBLK_PER_TAB, WPB * 32>>>(
        idx_pri, idx_sec, emb_pri, emb_sec, outp);
}